// round 15
// baseline (speedup 1.0000x reference)
#include <cuda_runtime.h>
#include <cuda_fp16.h>
#include <cstdint>

// ============================================================
// BayesianDenseLayer: out = x @ (w_loc + softplus(w_std)*eps_w) + b
// R15 = R14 GEMM (2 CTAs/SM, 128x128, 4 warps of 64x64, 3-stage
// ring, reg double buffer, head refill — 86.7% tensor) with:
//  - ONE fused prep kernel (W transpose+sample, A fp16 convert,
//    bias) instead of three launches: phases interleave across
//    SMs, HBM stays saturated, 2 launch gaps removed.
//  - rotating stage registers instead of %3 in the mainloop.
// ============================================================

#define DIN   4096
#define DOUT  4096
#define BATCH 8192

__device__ __half g_Wt[(size_t)DIN * DOUT];   // [DOUT][DIN], K contiguous, fp16
__device__ __half g_Ar[(size_t)BATCH * DIN];  // x in fp16
__device__ float  g_b[DOUT];

// ---------------- helpers ----------------

__device__ __forceinline__ uint32_t smem_u32(const void* p) {
    uint32_t a;
    asm("{ .reg .u64 t; cvta.to.shared.u64 t, %1; cvt.u32.u64 %0, t; }" : "=r"(a) : "l"(p));
    return a;
}

__device__ __forceinline__ float softplus_f(float x) {
    return fmaxf(x, 0.0f) + log1pf(expf(-fabsf(x)));
}

__device__ __forceinline__ void cp_async16(uint32_t dst, const void* src) {
    asm volatile("cp.async.cg.shared.global [%0], [%1], 16;" :: "r"(dst), "l"(src) : "memory");
}
__device__ __forceinline__ void cp_commit() {
    asm volatile("cp.async.commit_group;" ::: "memory");
}
__device__ __forceinline__ void cp_wait1() {
    asm volatile("cp.async.wait_group 1;" ::: "memory");
}

__device__ __forceinline__ void ldsm_x4(uint32_t* r, uint32_t addr) {
    asm volatile("ldmatrix.sync.aligned.m8n8.x4.shared.b16 {%0,%1,%2,%3}, [%4];"
                 : "=r"(r[0]), "=r"(r[1]), "=r"(r[2]), "=r"(r[3]) : "r"(addr));
}

__device__ __forceinline__ void mma_f16(float* c, const uint32_t* a, const uint32_t* b) {
    asm volatile(
        "mma.sync.aligned.m16n8k16.row.col.f32.f16.f16.f32 "
        "{%0,%1,%2,%3}, {%4,%5,%6,%7}, {%8,%9}, {%0,%1,%2,%3};"
        : "+f"(c[0]), "+f"(c[1]), "+f"(c[2]), "+f"(c[3])
        : "r"(a[0]), "r"(a[1]), "r"(a[2]), "r"(a[3]), "r"(b[0]), "r"(b[1]));
}

// ---------------- fused prep kernel ----------------
// blocks [0, 16384)          : W tiles (32x32 transpose + sample)
// blocks [16384, 16384+2048) : A fp16 conversion (grid-stride)
// blocks [16384+2048, +16)   : bias
static constexpr int PREP_W_BLOCKS = (DOUT / 32) * (DIN / 32);  // 16384
static constexpr int PREP_A_BLOCKS = 2048;
static constexpr int PREP_B_BLOCKS = DOUT / 256;                // 16
static constexpr int PREP_BLOCKS = PREP_W_BLOCKS + PREP_A_BLOCKS + PREP_B_BLOCKS;

__global__ void prep_fused_kernel(const float* __restrict__ wl,
                                  const float* __restrict__ ws,
                                  const float* __restrict__ ew,
                                  const float* __restrict__ x,
                                  const float* __restrict__ bl,
                                  const float* __restrict__ bsd,
                                  const float* __restrict__ eb) {
    __shared__ __half tile[32][33];
    int bid = blockIdx.x;
    int tid = threadIdx.x;

    if (bid < PREP_W_BLOCKS) {
        // ---- W: g_Wt[n][k] = fp16(w_loc + softplus(w_std)*eps_w) ----
        int n0 = (bid & (DOUT / 32 - 1)) * 32;
        int k0 = (bid >> 7) * 32;                 // DOUT/32 == 128 == 1<<7
        int tx = tid & 31, ty = tid >> 5;
        #pragma unroll
        for (int j = 0; j < 4; j++) {
            int k = k0 + ty + 8 * j;
            size_t idx = (size_t)k * DOUT + n0 + tx;
            float v = fmaf(softplus_f(ws[idx]), ew[idx], wl[idx]);
            tile[ty + 8 * j][tx] = __float2half_rn(v);
        }
        __syncthreads();
        #pragma unroll
        for (int j = 0; j < 4; j++) {
            int n = n0 + ty + 8 * j;
            g_Wt[(size_t)n * DIN + k0 + tx] = tile[tx][ty + 8 * j];
        }
    } else if (bid < PREP_W_BLOCKS + PREP_A_BLOCKS) {
        // ---- A: fp32 -> fp16 ----
        int ab = bid - PREP_W_BLOCKS;
        size_t i = (size_t)ab * 256 + tid;
        size_t n4 = (size_t)BATCH * DIN / 4;
        const float4* src = (const float4*)x;
        __half2* dst = (__half2*)g_Ar;
        for (; i < n4; i += (size_t)PREP_A_BLOCKS * 256) {
            float4 v = src[i];
            dst[2 * i]     = __floats2half2_rn(v.x, v.y);
            dst[2 * i + 1] = __floats2half2_rn(v.z, v.w);
        }
    } else {
        // ---- bias ----
        int i = (bid - PREP_W_BLOCKS - PREP_A_BLOCKS) * 256 + tid;
        if (i < DOUT) g_b[i] = fmaf(softplus_f(bsd[i]), eb[i], bl[i]);
    }
}

// ---------------- GEMM ----------------

static constexpr int BM = 128, BN = 128, BK = 64;       // BK in halves (128 B rows)
static constexpr int STAGES = 3;
static constexpr int STAGE_BYTES = (BM + BN) * BK * 2;  // 32 KB
static constexpr int B_OFF = BM * BK * 2;               // 16 KB within stage
static constexpr int KITERS = DIN / BK;                 // 64
static constexpr int NTHREADS = 128;                    // 4 warps; 2 CTAs/SM

__global__ __launch_bounds__(NTHREADS, 2)
void gemm_f16_kernel(const __half* __restrict__ A,   // g_Ar [BATCH][DIN]
                     const __half* __restrict__ B,   // g_Wt [DOUT][DIN]
                     const float* __restrict__ bias,
                     float* __restrict__ out) {
    extern __shared__ __align__(128) char smem[];
    uint32_t sbase = smem_u32(smem);

    int tid  = threadIdx.x;
    int lane = tid & 31;
    int warp = tid >> 5;
    int wm = warp & 1;          // 2 warps along M (64 each)
    int wn = warp >> 1;         // 2 warps along N (64 each)
    int m0 = blockIdx.y * BM;
    int n0 = blockIdx.x * BN;

    const __half* aSrcBase = A + (size_t)m0 * DIN;
    const __half* bSrcBase = B + (size_t)n0 * DIN;

    // cp.async: A = 1024 16B chunks (8/thread), B = 1024 (8/thread)
    auto copy_stage = [&](int s, int kt) {
        uint32_t st = sbase + s * STAGE_BYTES;
        int kbase = kt * BK;
        #pragma unroll
        for (int j = 0; j < 8; j++) {
            int cid = tid + j * NTHREADS;
            int m = cid >> 3, kc = cid & 7;
            cp_async16(st + m * 128 + ((kc * 16) ^ ((m & 7) << 4)),
                       aSrcBase + (size_t)m * DIN + kbase + kc * 8);
        }
        #pragma unroll
        for (int j = 0; j < 8; j++) {
            int cid = tid + j * NTHREADS;
            int n = cid >> 3, kc = cid & 7;
            cp_async16(st + B_OFF + n * 128 + ((kc * 16) ^ ((n & 7) << 4)),
                       bSrcBase + (size_t)n * DIN + kbase + kc * 8);
        }
    };

    // prologue: fill stages 0,1 (one commit group each)
    copy_stage(0, 0); cp_commit();
    copy_stage(1, 1); cp_commit();

    // ldmatrix per-thread bases
    int aRow = wm * 64 + (lane & 7) + ((lane >> 3) & 1) * 8;
    int aSel = ((lane >> 4) & 1) * 16;
    int bRow = wn * 64 + ((lane >> 4) & 1) * 8 + (lane & 7);
    int bSel = ((lane >> 3) & 1) * 16;
    uint32_t xorv = (uint32_t)(lane & 7) << 4;

    float acc[4][8][4];
    #pragma unroll
    for (int mi = 0; mi < 4; mi++)
        #pragma unroll
        for (int nj = 0; nj < 8; nj++)
            #pragma unroll
            for (int c = 0; c < 4; c++) acc[mi][nj][c] = 0.0f;

    uint32_t af[2][4][4], bf[2][4][4];

    auto load_group = [&](uint32_t (*afb)[4], uint32_t (*bfb)[4],
                          uint32_t sA, uint32_t sB, int ks) {
        uint32_t koff = (uint32_t)(ks * 32);
        #pragma unroll
        for (int mi = 0; mi < 4; mi++)
            ldsm_x4(afb[mi], sA + (uint32_t)(aRow + mi * 16) * 128
                             + ((koff + (uint32_t)aSel) ^ xorv));
        #pragma unroll
        for (int njp = 0; njp < 4; njp++)
            ldsm_x4(bfb[njp], sB + (uint32_t)(bRow + njp * 16) * 128
                              + ((koff + (uint32_t)bSel) ^ xorv));
    };

    auto mma_group = [&](uint32_t (*afb)[4], uint32_t (*bfb)[4]) {
        #pragma unroll
        for (int mi = 0; mi < 4; mi++)
            #pragma unroll
            for (int njp = 0; njp < 4; njp++) {
                mma_f16(acc[mi][2 * njp],     afb[mi], &bfb[njp][0]);
                mma_f16(acc[mi][2 * njp + 1], afb[mi], &bfb[njp][2]);
            }
    };

    cp_wait1();                 // stage 0 resident
    __syncthreads();
    load_group(af[0], bf[0], sbase, sbase + B_OFF, 0);

    // rotating stage slots: s_cur = k%3, s_nxt = (k+1)%3, s_fill = (k+2)%3
    int s_cur = 0, s_nxt = 1, s_fill = 2;

    #pragma unroll 1
    for (int k = 0; k < KITERS; k++) {
        uint32_t sA = sbase + (uint32_t)s_cur * STAGE_BYTES;
        uint32_t sB = sA + B_OFF;

        // HEAD refill: slot s_fill == (k-1)%3, drained before the barrier
        // that opened this iteration; committing here gives ~2-iter lead.
        if (k + 2 < KITERS) copy_stage(s_fill, k + 2);
        cp_commit();

        #pragma unroll
        for (int ks = 0; ks < 4; ks++) {
            if (ks < 3) {
                load_group(af[(ks + 1) & 1], bf[(ks + 1) & 1], sA, sB, ks + 1);
                mma_group(af[ks & 1], bf[ks & 1]);
            } else {
                mma_group(af[1], bf[1]);
                if (k + 1 < KITERS) {
                    cp_wait1();          // stage k+1 (committed at head of k-1)
                    __syncthreads();
                    uint32_t nA = sbase + (uint32_t)s_nxt * STAGE_BYTES;
                    load_group(af[0], bf[0], nA, nA + B_OFF, 0);
                }
            }
        }

        // rotate: next iter's fill slot is this iter's consume slot
        int t = s_cur;
        s_cur = s_nxt;
        s_nxt = s_fill;
        s_fill = t;
    }

    // -------- epilogue: add bias, store --------
    int g  = lane >> 2;
    int tg = lane & 3;
    #pragma unroll
    for (int nj = 0; nj < 8; nj++) {
        int col = n0 + wn * 64 + nj * 8 + tg * 2;
        float bx = bias[col], by = bias[col + 1];
        #pragma unroll
        for (int mi = 0; mi < 4; mi++) {
            int row = m0 + wm * 64 + mi * 16 + g;
            float2 v0 = make_float2(acc[mi][nj][0] + bx, acc[mi][nj][1] + by);
            float2 v1 = make_float2(acc[mi][nj][2] + bx, acc[mi][nj][3] + by);
            *reinterpret_cast<float2*>(out + (size_t)row * DOUT + col) = v0;
            *reinterpret_cast<float2*>(out + (size_t)(row + 8) * DOUT + col) = v1;
        }
    }
}

// ---------------- host launcher ----------------

extern "C" void kernel_launch(void* const* d_in, const int* in_sizes, int n_in,
                              void* d_out, int out_size) {
    const float* x   = (const float*)d_in[0];
    const float* wl  = (const float*)d_in[1];
    const float* ws  = (const float*)d_in[2];
    const float* bl  = (const float*)d_in[3];
    const float* bsd = (const float*)d_in[4];
    const float* ew  = (const float*)d_in[5];
    const float* eb  = (const float*)d_in[6];
    float* out = (float*)d_out;

    __half *wt_ptr = nullptr, *ar_ptr = nullptr;
    float *b_ptr = nullptr;
    cudaGetSymbolAddress((void**)&wt_ptr, g_Wt);
    cudaGetSymbolAddress((void**)&ar_ptr, g_Ar);
    cudaGetSymbolAddress((void**)&b_ptr,  g_b);

    // one fused prep launch: W sample+transpose, A fp16 convert, bias
    prep_fused_kernel<<<PREP_BLOCKS, 256>>>(wl, ws, ew, x, bl, bsd, eb);

    static bool attr_set = false;
    if (!attr_set) {
        cudaFuncSetAttribute(gemm_f16_kernel,
                             cudaFuncAttributeMaxDynamicSharedMemorySize,
                             STAGES * STAGE_BYTES);
        attr_set = true;
    }

    // N tiles fastest: CTAs in a row share A panel; W (32 MB fp16) stays in L2.
    gemm_f16_kernel<<<dim3(DOUT / BN, BATCH / BM), NTHREADS, STAGES * STAGE_BYTES>>>(
        ar_ptr, wt_ptr, b_ptr, out);
}

// round 16
// speedup vs baseline: 1.0161x; 1.0161x over previous
#include <cuda_runtime.h>
#include <cuda_fp16.h>
#include <cstdint>

// ============================================================
// BayesianDenseLayer: out = x @ (w_loc + softplus(w_std)*eps_w) + b
// R16 = recombination of measured wins:
//  - GEMM: byte-identical to R14 (best GEMM, 605.7us / 86.7%
//    tensor): 2 CTAs/SM, 128x128 tile, 4 warps of 64x64, 3-stage
//    ring with %3 indexing, reg double buffer, head refill.
//    (R15's rotating-slot registers regressed it; reverted.)
//  - Prep: R15's single fused kernel (27.9us vs 39.8us for three
//    launches): W sample+transpose, A fp16 convert, bias.
// ============================================================

#define DIN   4096
#define DOUT  4096
#define BATCH 8192

__device__ __half g_Wt[(size_t)DIN * DOUT];   // [DOUT][DIN], K contiguous, fp16
__device__ __half g_Ar[(size_t)BATCH * DIN];  // x in fp16
__device__ float  g_b[DOUT];

// ---------------- helpers ----------------

__device__ __forceinline__ uint32_t smem_u32(const void* p) {
    uint32_t a;
    asm("{ .reg .u64 t; cvta.to.shared.u64 t, %1; cvt.u32.u64 %0, t; }" : "=r"(a) : "l"(p));
    return a;
}

__device__ __forceinline__ float softplus_f(float x) {
    return fmaxf(x, 0.0f) + log1pf(expf(-fabsf(x)));
}

__device__ __forceinline__ void cp_async16(uint32_t dst, const void* src) {
    asm volatile("cp.async.cg.shared.global [%0], [%1], 16;" :: "r"(dst), "l"(src) : "memory");
}
__device__ __forceinline__ void cp_commit() {
    asm volatile("cp.async.commit_group;" ::: "memory");
}
__device__ __forceinline__ void cp_wait1() {
    asm volatile("cp.async.wait_group 1;" ::: "memory");
}

__device__ __forceinline__ void ldsm_x4(uint32_t* r, uint32_t addr) {
    asm volatile("ldmatrix.sync.aligned.m8n8.x4.shared.b16 {%0,%1,%2,%3}, [%4];"
                 : "=r"(r[0]), "=r"(r[1]), "=r"(r[2]), "=r"(r[3]) : "r"(addr));
}

__device__ __forceinline__ void mma_f16(float* c, const uint32_t* a, const uint32_t* b) {
    asm volatile(
        "mma.sync.aligned.m16n8k16.row.col.f32.f16.f16.f32 "
        "{%0,%1,%2,%3}, {%4,%5,%6,%7}, {%8,%9}, {%0,%1,%2,%3};"
        : "+f"(c[0]), "+f"(c[1]), "+f"(c[2]), "+f"(c[3])
        : "r"(a[0]), "r"(a[1]), "r"(a[2]), "r"(a[3]), "r"(b[0]), "r"(b[1]));
}

// ---------------- fused prep kernel ----------------
// blocks [0, 16384)          : W tiles (32x32 transpose + sample)
// blocks [16384, 16384+2048) : A fp16 conversion (grid-stride)
// blocks [16384+2048, +16)   : bias
static constexpr int PREP_W_BLOCKS = (DOUT / 32) * (DIN / 32);  // 16384
static constexpr int PREP_A_BLOCKS = 2048;
static constexpr int PREP_B_BLOCKS = DOUT / 256;                // 16
static constexpr int PREP_BLOCKS = PREP_W_BLOCKS + PREP_A_BLOCKS + PREP_B_BLOCKS;

__global__ void prep_fused_kernel(const float* __restrict__ wl,
                                  const float* __restrict__ ws,
                                  const float* __restrict__ ew,
                                  const float* __restrict__ x,
                                  const float* __restrict__ bl,
                                  const float* __restrict__ bsd,
                                  const float* __restrict__ eb) {
    __shared__ __half tile[32][33];
    int bid = blockIdx.x;
    int tid = threadIdx.x;

    if (bid < PREP_W_BLOCKS) {
        // ---- W: g_Wt[n][k] = fp16(w_loc + softplus(w_std)*eps_w) ----
        int n0 = (bid & (DOUT / 32 - 1)) * 32;
        int k0 = (bid >> 7) * 32;                 // DOUT/32 == 128 == 1<<7
        int tx = tid & 31, ty = tid >> 5;
        #pragma unroll
        for (int j = 0; j < 4; j++) {
            int k = k0 + ty + 8 * j;
            size_t idx = (size_t)k * DOUT + n0 + tx;
            float v = fmaf(softplus_f(ws[idx]), ew[idx], wl[idx]);
            tile[ty + 8 * j][tx] = __float2half_rn(v);
        }
        __syncthreads();
        #pragma unroll
        for (int j = 0; j < 4; j++) {
            int n = n0 + ty + 8 * j;
            g_Wt[(size_t)n * DIN + k0 + tx] = tile[tx][ty + 8 * j];
        }
    } else if (bid < PREP_W_BLOCKS + PREP_A_BLOCKS) {
        // ---- A: fp32 -> fp16 ----
        int ab = bid - PREP_W_BLOCKS;
        size_t i = (size_t)ab * 256 + tid;
        size_t n4 = (size_t)BATCH * DIN / 4;
        const float4* src = (const float4*)x;
        __half2* dst = (__half2*)g_Ar;
        for (; i < n4; i += (size_t)PREP_A_BLOCKS * 256) {
            float4 v = src[i];
            dst[2 * i]     = __floats2half2_rn(v.x, v.y);
            dst[2 * i + 1] = __floats2half2_rn(v.z, v.w);
        }
    } else {
        // ---- bias ----
        int i = (bid - PREP_W_BLOCKS - PREP_A_BLOCKS) * 256 + tid;
        if (i < DOUT) g_b[i] = fmaf(softplus_f(bsd[i]), eb[i], bl[i]);
    }
}

// ---------------- GEMM (byte-identical mainloop to R14) ----------------

static constexpr int BM = 128, BN = 128, BK = 64;       // BK in halves (128 B rows)
static constexpr int STAGES = 3;
static constexpr int STAGE_BYTES = (BM + BN) * BK * 2;  // 32 KB
static constexpr int B_OFF = BM * BK * 2;               // 16 KB within stage
static constexpr int KITERS = DIN / BK;                 // 64
static constexpr int NTHREADS = 128;                    // 4 warps; 2 CTAs/SM

__global__ __launch_bounds__(NTHREADS, 2)
void gemm_f16_kernel(const __half* __restrict__ A,   // g_Ar [BATCH][DIN]
                     const __half* __restrict__ B,   // g_Wt [DOUT][DIN]
                     const float* __restrict__ bias,
                     float* __restrict__ out) {
    extern __shared__ __align__(128) char smem[];
    uint32_t sbase = smem_u32(smem);

    int tid  = threadIdx.x;
    int lane = tid & 31;
    int warp = tid >> 5;
    int wm = warp & 1;          // 2 warps along M (64 each)
    int wn = warp >> 1;         // 2 warps along N (64 each)
    int m0 = blockIdx.y * BM;
    int n0 = blockIdx.x * BN;

    const __half* aSrcBase = A + (size_t)m0 * DIN;
    const __half* bSrcBase = B + (size_t)n0 * DIN;

    // cp.async: A = 1024 16B chunks (8/thread), B = 1024 (8/thread)
    auto copy_stage = [&](int s, int kt) {
        uint32_t st = sbase + s * STAGE_BYTES;
        int kbase = kt * BK;
        #pragma unroll
        for (int j = 0; j < 8; j++) {
            int cid = tid + j * NTHREADS;
            int m = cid >> 3, kc = cid & 7;
            cp_async16(st + m * 128 + ((kc * 16) ^ ((m & 7) << 4)),
                       aSrcBase + (size_t)m * DIN + kbase + kc * 8);
        }
        #pragma unroll
        for (int j = 0; j < 8; j++) {
            int cid = tid + j * NTHREADS;
            int n = cid >> 3, kc = cid & 7;
            cp_async16(st + B_OFF + n * 128 + ((kc * 16) ^ ((n & 7) << 4)),
                       bSrcBase + (size_t)n * DIN + kbase + kc * 8);
        }
    };

    // prologue: fill stages 0,1 (one commit group each)
    copy_stage(0, 0); cp_commit();
    copy_stage(1, 1); cp_commit();

    // ldmatrix per-thread bases
    int aRow = wm * 64 + (lane & 7) + ((lane >> 3) & 1) * 8;
    int aSel = ((lane >> 4) & 1) * 16;
    int bRow = wn * 64 + ((lane >> 4) & 1) * 8 + (lane & 7);
    int bSel = ((lane >> 3) & 1) * 16;
    uint32_t xorv = (uint32_t)(lane & 7) << 4;

    float acc[4][8][4];
    #pragma unroll
    for (int mi = 0; mi < 4; mi++)
        #pragma unroll
        for (int nj = 0; nj < 8; nj++)
            #pragma unroll
            for (int c = 0; c < 4; c++) acc[mi][nj][c] = 0.0f;

    uint32_t af[2][4][4], bf[2][4][4];

    auto load_group = [&](uint32_t (*afb)[4], uint32_t (*bfb)[4],
                          uint32_t sA, uint32_t sB, int ks) {
        uint32_t koff = (uint32_t)(ks * 32);
        #pragma unroll
        for (int mi = 0; mi < 4; mi++)
            ldsm_x4(afb[mi], sA + (uint32_t)(aRow + mi * 16) * 128
                             + ((koff + (uint32_t)aSel) ^ xorv));
        #pragma unroll
        for (int njp = 0; njp < 4; njp++)
            ldsm_x4(bfb[njp], sB + (uint32_t)(bRow + njp * 16) * 128
                              + ((koff + (uint32_t)bSel) ^ xorv));
    };

    auto mma_group = [&](uint32_t (*afb)[4], uint32_t (*bfb)[4]) {
        #pragma unroll
        for (int mi = 0; mi < 4; mi++)
            #pragma unroll
            for (int njp = 0; njp < 4; njp++) {
                mma_f16(acc[mi][2 * njp],     afb[mi], &bfb[njp][0]);
                mma_f16(acc[mi][2 * njp + 1], afb[mi], &bfb[njp][2]);
            }
    };

    cp_wait1();                 // stage 0 resident
    __syncthreads();
    load_group(af[0], bf[0], sbase, sbase + B_OFF, 0);

    #pragma unroll 1
    for (int k = 0; k < KITERS; k++) {
        uint32_t sA = sbase + (uint32_t)(k % 3) * STAGE_BYTES;
        uint32_t sB = sA + B_OFF;

        // HEAD refill: stage k+2 into slot (k+2)%3 == (k-1)%3, which all
        // warps drained before the barrier that opened this iteration.
        // Committing here (instead of at the tail) doubles the prefetch
        // lead for the wait at the end of this iteration.
        if (k + 2 < KITERS) copy_stage((k + 2) % 3, k + 2);
        cp_commit();

        #pragma unroll
        for (int ks = 0; ks < 4; ks++) {
            if (ks < 3) {
                load_group(af[(ks + 1) & 1], bf[(ks + 1) & 1], sA, sB, ks + 1);
                mma_group(af[ks & 1], bf[ks & 1]);
            } else {
                mma_group(af[1], bf[1]);
                if (k + 1 < KITERS) {
                    cp_wait1();          // stage k+1 (committed at head of k-1)
                    __syncthreads();
                    uint32_t nA = sbase + (uint32_t)((k + 1) % 3) * STAGE_BYTES;
                    load_group(af[0], bf[0], nA, nA + B_OFF, 0);
                }
            }
        }
    }

    // -------- epilogue: add bias, store --------
    int g  = lane >> 2;
    int tg = lane & 3;
    #pragma unroll
    for (int nj = 0; nj < 8; nj++) {
        int col = n0 + wn * 64 + nj * 8 + tg * 2;
        float bx = bias[col], by = bias[col + 1];
        #pragma unroll
        for (int mi = 0; mi < 4; mi++) {
            int row = m0 + wm * 64 + mi * 16 + g;
            float2 v0 = make_float2(acc[mi][nj][0] + bx, acc[mi][nj][1] + by);
            float2 v1 = make_float2(acc[mi][nj][2] + bx, acc[mi][nj][3] + by);
            *reinterpret_cast<float2*>(out + (size_t)row * DOUT + col) = v0;
            *reinterpret_cast<float2*>(out + (size_t)(row + 8) * DOUT + col) = v1;
        }
    }
}

// ---------------- host launcher ----------------

extern "C" void kernel_launch(void* const* d_in, const int* in_sizes, int n_in,
                              void* d_out, int out_size) {
    const float* x   = (const float*)d_in[0];
    const float* wl  = (const float*)d_in[1];
    const float* ws  = (const float*)d_in[2];
    const float* bl  = (const float*)d_in[3];
    const float* bsd = (const float*)d_in[4];
    const float* ew  = (const float*)d_in[5];
    const float* eb  = (const float*)d_in[6];
    float* out = (float*)d_out;

    __half *wt_ptr = nullptr, *ar_ptr = nullptr;
    float *b_ptr = nullptr;
    cudaGetSymbolAddress((void**)&wt_ptr, g_Wt);
    cudaGetSymbolAddress((void**)&ar_ptr, g_Ar);
    cudaGetSymbolAddress((void**)&b_ptr,  g_b);

    // one fused prep launch: W sample+transpose, A fp16 convert, bias
    prep_fused_kernel<<<PREP_BLOCKS, 256>>>(wl, ws, ew, x, bl, bsd, eb);

    static bool attr_set = false;
    if (!attr_set) {
        cudaFuncSetAttribute(gemm_f16_kernel,
                             cudaFuncAttributeMaxDynamicSharedMemorySize,
                             STAGES * STAGE_BYTES);
        attr_set = true;
    }

    // N tiles fastest: CTAs in a row share A panel; W (32 MB fp16) stays in L2.
    gemm_f16_kernel<<<dim3(DOUT / BN, BATCH / BM), NTHREADS, STAGES * STAGE_BYTES>>>(
        ar_ptr, wt_ptr, b_ptr, out);
}